// round 1
// baseline (speedup 1.0000x reference)
#include <cuda_runtime.h>
#include <cstdint>

#define MAXM 8192
#define MAXN 8192
#define KCAND 64
#define GT_TILE 2048

// ---------------- device scratch (no allocations allowed) ----------------
__device__ int                 g_cnt[MAXM];
__device__ unsigned long long  g_keys[MAXM * KCAND];     // (fbits(dsq)<<32)|j, unsorted
__device__ unsigned short      g_sorted[MAXM * KCAND];   // j sorted by (dsq, j)
__device__ int                 g_match[MAXM];            // matched gt index or -1
__device__ float               g_acc[5];                 // Sc, Ss, So, Si, count

// ---------------- init ----------------
__global__ void init_kernel(int m) {
    int i = blockIdx.x * blockDim.x + threadIdx.x;
    if (i < m) g_cnt[i] = 0;
    if (i < 5) g_acc[i] = 0.0f;
}

// ---------------- phase 1: candidate generation ----------------
// grid: (m/128, n/GT_TILE), block: 128. Each thread owns one pred row,
// iterates a gt tile staged in smem (warp-broadcast reads).
__global__ void cand_kernel(const float* __restrict__ pred,
                            const float* __restrict__ gt,
                            int m, int n) {
    __shared__ float sx[GT_TILE], sy[GT_TILE], sz[GT_TILE];
    int jbase  = blockIdx.y * GT_TILE;
    int jcount = min(GT_TILE, n - jbase);
    for (int t = threadIdx.x; t < jcount; t += blockDim.x) {
        int r = jbase + t;
        sx[t] = gt[r * 7 + 0];
        sy[t] = gt[r * 7 + 1];
        sz[t] = gt[r * 7 + 2];
    }
    __syncthreads();

    int i = blockIdx.x * blockDim.x + threadIdx.x;
    if (i >= m) return;
    float px = pred[i * 7 + 0];
    float py = pred[i * 7 + 1];
    float pz = pred[i * 7 + 2];

    for (int t = 0; t < jcount; ++t) {
        float dx = px - sx[t];
        float dy = py - sy[t];
        float dz = pz - sz[t];
        float dsq = fmaf(dx, dx, fmaf(dy, dy, dz * dz));
        if (dsq < 25.0f) {                       // dist < MATCH_THRESH=5
            int pos = atomicAdd(&g_cnt[i], 1);
            if (pos < KCAND) {
                unsigned long long key =
                    ((unsigned long long)__float_as_uint(dsq) << 32) |
                    (unsigned)(jbase + t);
                g_keys[i * KCAND + pos] = key;
            }
        }
    }
}

// ---------------- phase 2: per-row sort (counts ~4-5, insertion sort) ------
__global__ void sort_kernel(int m) {
    int i = blockIdx.x * blockDim.x + threadIdx.x;
    if (i >= m) return;
    int nc = min(g_cnt[i], KCAND);
    g_cnt[i] = nc;
    unsigned long long a[KCAND];
    for (int c = 0; c < nc; ++c) a[c] = g_keys[i * KCAND + c];
    for (int c = 1; c < nc; ++c) {
        unsigned long long v = a[c];
        int d = c;
        while (d > 0 && a[d - 1] > v) { a[d] = a[d - 1]; --d; }
        a[d] = v;
    }
    for (int c = 0; c < nc; ++c)
        g_sorted[i * KCAND + c] = (unsigned short)(a[c] & 0xFFFFu);
}

// ---------------- phase 3: warp-speculative greedy matcher -----------------
// Single block. Stage first-8 candidates of every row + counts + avail in
// SMEM, then warp 0 processes rows in batches of 32.
// Correctness lemma: distinct simultaneous choices w.r.t. current avail all
// commit and equal the sequential greedy result; duplicates resolved by a
// monotone prefix-finalization loop (fb strictly increases each iteration).
extern __shared__ unsigned char smem_raw[];
__global__ void match_kernel(int m, int n) {
    unsigned short* s_cand  = (unsigned short*)smem_raw;             // MAXM*8
    unsigned char*  s_cnt   = (unsigned char*)(s_cand + MAXM * 8);   // MAXM
    unsigned char*  s_avail = s_cnt + MAXM;                          // MAXN
    int tid = threadIdx.x;

    for (int i = tid; i < m; i += blockDim.x) {
        int c = g_cnt[i];
        s_cnt[i] = (unsigned char)c;
        int lim = min(c, 8);
        for (int p = 0; p < lim; ++p)
            s_cand[i * 8 + p] = g_sorted[i * KCAND + p];
    }
    for (int j = tid; j < n; j += blockDim.x) s_avail[j] = 1;
    __syncthreads();

    if (tid < 32) {
        const unsigned FULL = 0xFFFFFFFFu;
        for (int base = 0; base < m; base += 32) {
            int i = base + tid;
            int cnt = (i < m) ? (int)s_cnt[i] : 0;
            int pos = 0, choice = -1;
            for (; pos < cnt; ++pos) {
                int j = (pos < 8) ? (int)s_cand[i * 8 + pos]
                                  : (int)g_sorted[i * KCAND + pos];
                if (s_avail[j]) { choice = j; break; }
            }
            int fb = 0;
            while (true) {
                bool active = (tid >= fb) && (choice >= 0);
                unsigned key = active ? (unsigned)choice : (0x80000000u | tid);
                unsigned peers = __match_any_sync(FULL, key);
                int leader = __ffs(peers) - 1;
                bool loser = active && (tid != leader);
                unsigned loserMask = __ballot_sync(FULL, loser);
                if (loserMask == 0) {
                    if (active) s_avail[choice] = 0;   // all distinct: commit
                    break;
                }
                int Ll = __ffs(loserMask) - 1;          // lowest loser lane
                if (active && tid < Ll) s_avail[choice] = 0;  // prefix final
                __syncwarp(FULL);
                if (tid >= Ll && choice >= 0 && s_avail[choice] == 0) {
                    choice = -1; ++pos;                 // stolen -> rescan
                    for (; pos < cnt; ++pos) {
                        int j = (pos < 8) ? (int)s_cand[i * 8 + pos]
                                          : (int)g_sorted[i * KCAND + pos];
                        if (s_avail[j]) { choice = j; break; }
                    }
                }
                fb = Ll;
                __syncwarp(FULL);
            }
            if (i < m) g_match[i] = choice;
        }
    }
    __syncthreads();
}

// ---------------- phase 4: loss reduction ----------------
__device__ __forceinline__ float sl1(float x) {
    float a = fabsf(x);
    return (a < 1.0f) ? 0.5f * a * a : a - 0.5f;
}

__global__ void loss_kernel(const float* __restrict__ pred,
                            const float* __restrict__ gt, int m) {
    int i = blockIdx.x * blockDim.x + threadIdx.x;
    float sc = 0.f, ss = 0.f, so = 0.f, si = 0.f, cf = 0.f;
    if (i < m) {
        int j = g_match[i];
        if (j >= 0) {
            cf = 1.0f;
            const float* p = pred + i * 7;
            const float* g = gt + j * 7;
            sc = sl1(p[0] - g[0]) + sl1(p[1] - g[1]) + sl1(p[2] - g[2]);
            ss = sl1(p[3] - g[3]) + sl1(p[4] - g[4]) + sl1(p[5] - g[5]);
            float dth = p[6] - g[6];
            dth = atan2f(sinf(dth), cosf(dth));
            so = sl1(dth);
            float x1 = p[0], y1 = p[1], l1 = p[3], w1 = p[4];
            float x2 = g[0], y2 = g[1], l2 = g[3], w2 = g[4];
            float iw = fminf(x1 + l1 * 0.5f, x2 + l2 * 0.5f)
                     - fmaxf(x1 - l1 * 0.5f, x2 - l2 * 0.5f);
            iw = fmaxf(iw, 0.0f);
            float ih = fminf(y1 + w1 * 0.5f, y2 + w2 * 0.5f)
                     - fmaxf(y1 - w1 * 0.5f, y2 - w2 * 0.5f);
            ih = fmaxf(ih, 0.0f);
            float inter = iw * ih;
            float uni = l1 * w1 + l2 * w2 - inter;
            float iou = inter / (uni + 1e-6f);
            si = 1.0f - iou;
        }
    }
    #pragma unroll
    for (int o = 16; o; o >>= 1) {
        sc += __shfl_down_sync(0xFFFFFFFFu, sc, o);
        ss += __shfl_down_sync(0xFFFFFFFFu, ss, o);
        so += __shfl_down_sync(0xFFFFFFFFu, so, o);
        si += __shfl_down_sync(0xFFFFFFFFu, si, o);
        cf += __shfl_down_sync(0xFFFFFFFFu, cf, o);
    }
    if ((threadIdx.x & 31) == 0) {
        atomicAdd(&g_acc[0], sc);
        atomicAdd(&g_acc[1], ss);
        atomicAdd(&g_acc[2], so);
        atomicAdd(&g_acc[3], si);
        atomicAdd(&g_acc[4], cf);
    }
}

__global__ void finalize_kernel(float* out) {
    float k  = fmaxf(g_acc[4], 1.0f);
    float lc = g_acc[0] / (3.0f * k);
    float ls = g_acc[1] / (3.0f * k);
    float lo = g_acc[2] / k;
    float li = g_acc[3] / k;
    out[0] = 1.0f * lc + 0.5f * (ls + lo) + 2.0f * li;
}

// ---------------- launch ----------------
extern "C" void kernel_launch(void* const* d_in, const int* in_sizes, int n_in,
                              void* d_out, int out_size) {
    const float* pred = (const float*)d_in[0];
    const float* gt   = (const float*)d_in[1];
    int m = in_sizes[0] / 7;
    int n = in_sizes[1] / 7;

    init_kernel<<<(m + 255) / 256, 256>>>(m);

    dim3 g1((m + 127) / 128, (n + GT_TILE - 1) / GT_TILE);
    cand_kernel<<<g1, 128>>>(pred, gt, m, n);

    sort_kernel<<<(m + 127) / 128, 128>>>(m);

    size_t smem = (size_t)MAXM * 8 * sizeof(unsigned short) + MAXM + MAXN;
    cudaFuncSetAttribute(match_kernel,
                         cudaFuncAttributeMaxDynamicSharedMemorySize,
                         (int)smem);
    match_kernel<<<1, 1024, smem>>>(m, n);

    loss_kernel<<<(m + 255) / 256, 256>>>(pred, gt, m);
    finalize_kernel<<<1, 1>>>((float*)d_out);
}

// round 2
// speedup vs baseline: 1.0215x; 1.0215x over previous
#include <cuda_runtime.h>
#include <cstdint>

#define MAXM 8192
#define MAXN 8192
#define KCAND 64
#define GT_TILE 512

typedef unsigned long long u64;

// ---------------- device scratch (no allocations allowed) ----------------
__device__ int            g_cnt[MAXM];
__device__ u64            g_keys[MAXM * KCAND];    // (fbits(dsq)<<32)|j, arrival order
__device__ unsigned short g_sorted[MAXM * KCAND];  // deep (pos>=8) sorted candidates
__device__ int            g_match[MAXM];           // matched gt index or -1
__device__ float          g_acc[5];                // Sc, Ss, So, Si, count
__device__ unsigned       g_done;

// ---------------- init ----------------
__global__ void init_kernel(int m) {
    int i = blockIdx.x * blockDim.x + threadIdx.x;
    if (i < m) g_cnt[i] = 0;
    if (i < 5) g_acc[i] = 0.0f;
    if (i == 0) g_done = 0u;
}

// ---------------- phase 1: candidate generation ----------------
// Each thread owns TWO pred rows (i, i+m/2); gt centers staged in smem
// (warp-broadcast reads). Fused min-compare so the hit branch is one test.
__global__ void cand_kernel(const float* __restrict__ pred,
                            const float* __restrict__ gt,
                            int m, int n) {
    __shared__ float sx[GT_TILE], sy[GT_TILE], sz[GT_TILE];
    int jbase  = blockIdx.y * GT_TILE;
    int jcount = min(GT_TILE, n - jbase);
    for (int t = threadIdx.x; t < jcount; t += blockDim.x) {
        const float* g = gt + (size_t)(jbase + t) * 7;
        sx[t] = g[0]; sy[t] = g[1]; sz[t] = g[2];
    }
    __syncthreads();

    int half = (m + 1) >> 1;
    int i1 = blockIdx.x * blockDim.x + threadIdx.x;
    if (i1 >= half) return;
    int i2 = i1 + half;
    bool has2 = (i2 < m);

    float px1 = pred[i1 * 7 + 0], py1 = pred[i1 * 7 + 1], pz1 = pred[i1 * 7 + 2];
    float px2 = 1e30f, py2 = 1e30f, pz2 = 1e30f;
    if (has2) { px2 = pred[i2 * 7 + 0]; py2 = pred[i2 * 7 + 1]; pz2 = pred[i2 * 7 + 2]; }

    #pragma unroll 4
    for (int t = 0; t < jcount; ++t) {
        float gx = sx[t], gy = sy[t], gz = sz[t];
        float dx = px1 - gx, dy = py1 - gy, dz = pz1 - gz;
        float d1 = fmaf(dx, dx, fmaf(dy, dy, dz * dz));
        dx = px2 - gx; dy = py2 - gy; dz = pz2 - gz;
        float d2 = fmaf(dx, dx, fmaf(dy, dy, dz * dz));
        if (fminf(d1, d2) < 25.0f) {
            int j = jbase + t;
            if (d1 < 25.0f) {
                int p = atomicAdd(&g_cnt[i1], 1);
                if (p < KCAND)
                    g_keys[i1 * KCAND + p] =
                        ((u64)__float_as_uint(d1) << 32) | (unsigned)j;
            }
            if (d2 < 25.0f) {
                int p = atomicAdd(&g_cnt[i2], 1);
                if (p < KCAND)
                    g_keys[i2 * KCAND + p] =
                        ((u64)__float_as_uint(d2) << 32) | (unsigned)j;
            }
        }
    }
}

// ---------------- phase 2+3: fused sort + warp-speculative greedy matcher --
// Single block. 1024 threads sort each row's candidates (counts ~4-5,
// insertion sort) and stage top-8 in SMEM; warp 0 then runs the greedy
// matcher 32 rows/batch with bitmask speculation.
// Safety of batch-start avail snapshot: avail is monotone (1->0). A stale 1
// can only come from a commit by a lane in the SAME batch, which is exactly
// what __match_any_sync detects and the prefix-finalization loop resolves
// (identical logic to the round-1 kernel that matched exactly).
extern __shared__ unsigned char smem_raw[];
__global__ void match_kernel(int m, int n) {
    unsigned short* s_cand  = (unsigned short*)smem_raw;             // MAXM*8
    unsigned char*  s_cnt   = (unsigned char*)(s_cand + MAXM * 8);   // MAXM
    unsigned char*  s_avail = s_cnt + MAXM;                          // MAXN
    int tid = threadIdx.x;

    // --- staging: per-row sort, top-8 -> smem, overflow -> g_sorted ---
    for (int i = tid; i < m; i += blockDim.x) {
        int nc = min(g_cnt[i], KCAND);
        s_cnt[i] = (unsigned char)nc;
        u64 a[KCAND];
        for (int c = 0; c < nc; ++c) a[c] = g_keys[(size_t)i * KCAND + c];
        for (int c = 1; c < nc; ++c) {
            u64 v = a[c]; int d = c;
            while (d > 0 && a[d - 1] > v) { a[d] = a[d - 1]; --d; }
            a[d] = v;
        }
        unsigned short c8[8] = {0, 0, 0, 0, 0, 0, 0, 0};
        int lim = min(nc, 8);
        for (int c = 0; c < lim; ++c) c8[c] = (unsigned short)(a[c] & 0xFFFFu);
        uint4 v4;
        v4.x = (unsigned)c8[0] | ((unsigned)c8[1] << 16);
        v4.y = (unsigned)c8[2] | ((unsigned)c8[3] << 16);
        v4.z = (unsigned)c8[4] | ((unsigned)c8[5] << 16);
        v4.w = (unsigned)c8[6] | ((unsigned)c8[7] << 16);
        *(uint4*)(s_cand + (size_t)i * 8) = v4;
        for (int c = 8; c < nc; ++c)
            g_sorted[(size_t)i * KCAND + c] = (unsigned short)(a[c] & 0xFFFFu);
    }
    for (int j = tid; j < n; j += blockDim.x) s_avail[j] = 1;
    __syncthreads();

    if (tid < 32) {
        const unsigned FULL = 0xFFFFFFFFu;
        // prefetch first batch
        uint4 cv = *(const uint4*)(s_cand + (size_t)tid * 8);
        int   pcnt = (tid < m) ? (int)s_cnt[tid] : 0;

        for (int base = 0; base < m; base += 32) {
            int i = base + tid;
            uint4 cur = cv;
            int ccnt = (i < m) ? pcnt : 0;
            if (base + 32 < m) {   // prefetch next batch (static data)
                cv   = *(const uint4*)(s_cand + (size_t)(i + 32) * 8);
                pcnt = (int)s_cnt[i + 32];
            }
            u64 lo = (u64)cur.x | ((u64)cur.y << 32);
            u64 hi = (u64)cur.z | ((u64)cur.w << 32);
            auto getc = [&](int k) -> int {
                u64 w = (k < 4) ? lo : hi;
                return (int)((w >> ((k & 3) * 16)) & 0xFFFFu);
            };
            // 8 independent avail probes -> bitmask
            unsigned wm = 0;
            #pragma unroll
            for (int k = 0; k < 8; ++k)
                wm |= ((unsigned)s_avail[getc(k)] & 1u) << k;
            int lim = min(ccnt, 8);
            wm &= (unsigned)((1u << lim) - 1u);

            int posd = 8, kcur = -1, choice = -1;
            auto pick = [&]() -> int {
                while (wm) {
                    int k = __ffs(wm) - 1;
                    int j = getc(k);
                    if (s_avail[j]) { kcur = k; return j; }
                    wm &= wm - 1;
                }
                kcur = -1;
                while (posd < ccnt) {       // deep candidates (rare)
                    int j = (int)g_sorted[(size_t)i * KCAND + posd];
                    ++posd;
                    if (s_avail[j]) return j;
                }
                return -1;
            };
            if (wm) { int k = __ffs(wm) - 1; kcur = k; choice = getc(k); }
            else if (ccnt > 8) choice = pick();

            int fb = 0;
            while (true) {
                bool active = (tid >= fb) && (choice >= 0);
                unsigned key = active ? (unsigned)choice : (0x80000000u | tid);
                unsigned peers = __match_any_sync(FULL, key);
                bool loser = active && (tid != (__ffs(peers) - 1));
                unsigned lm = __ballot_sync(FULL, loser);
                if (lm == 0u) {
                    if (active) s_avail[choice] = 0;   // all distinct: commit
                    break;
                }
                int Ll = __ffs(lm) - 1;                 // lowest loser lane
                if (active && tid < Ll) s_avail[choice] = 0;  // prefix final
                __syncwarp(FULL);
                if (tid >= Ll && choice >= 0 && s_avail[choice] == 0) {
                    if (kcur >= 0) wm &= ~(1u << kcur); // stolen -> rescan
                    choice = pick();
                }
                fb = Ll;
                __syncwarp(FULL);
            }
            if (i < m) g_match[i] = choice;
            __syncwarp(FULL);   // commits visible before next batch's probes
        }
    }
    __syncthreads();
}

// ---------------- phase 4: loss reduction + fused finalize ----------------
__device__ __forceinline__ float sl1(float x) {
    float a = fabsf(x);
    return (a < 1.0f) ? 0.5f * a * a : a - 0.5f;
}

__global__ void loss_kernel(const float* __restrict__ pred,
                            const float* __restrict__ gt,
                            int m, float* out) {
    __shared__ bool isLast;
    int i = blockIdx.x * blockDim.x + threadIdx.x;
    float sc = 0.f, ss = 0.f, so = 0.f, si = 0.f, cf = 0.f;
    if (i < m) {
        int j = g_match[i];
        if (j >= 0) {
            cf = 1.0f;
            const float* p = pred + (size_t)i * 7;
            const float* g = gt + (size_t)j * 7;
            sc = sl1(p[0] - g[0]) + sl1(p[1] - g[1]) + sl1(p[2] - g[2]);
            ss = sl1(p[3] - g[3]) + sl1(p[4] - g[4]) + sl1(p[5] - g[5]);
            float dth = p[6] - g[6];
            dth = atan2f(sinf(dth), cosf(dth));
            so = sl1(dth);
            float x1 = p[0], y1 = p[1], l1 = p[3], w1 = p[4];
            float x2 = g[0], y2 = g[1], l2 = g[3], w2 = g[4];
            float iw = fminf(x1 + l1 * 0.5f, x2 + l2 * 0.5f)
                     - fmaxf(x1 - l1 * 0.5f, x2 - l2 * 0.5f);
            iw = fmaxf(iw, 0.0f);
            float ih = fminf(y1 + w1 * 0.5f, y2 + w2 * 0.5f)
                     - fmaxf(y1 - w1 * 0.5f, y2 - w2 * 0.5f);
            ih = fmaxf(ih, 0.0f);
            float inter = iw * ih;
            float uni = l1 * w1 + l2 * w2 - inter;
            si = 1.0f - inter / (uni + 1e-6f);
        }
    }
    #pragma unroll
    for (int o = 16; o; o >>= 1) {
        sc += __shfl_down_sync(0xFFFFFFFFu, sc, o);
        ss += __shfl_down_sync(0xFFFFFFFFu, ss, o);
        so += __shfl_down_sync(0xFFFFFFFFu, so, o);
        si += __shfl_down_sync(0xFFFFFFFFu, si, o);
        cf += __shfl_down_sync(0xFFFFFFFFu, cf, o);
    }
    if ((threadIdx.x & 31) == 0) {
        atomicAdd(&g_acc[0], sc);
        atomicAdd(&g_acc[1], ss);
        atomicAdd(&g_acc[2], so);
        atomicAdd(&g_acc[3], si);
        atomicAdd(&g_acc[4], cf);
    }
    __syncthreads();
    if (threadIdx.x == 0) {
        __threadfence();
        unsigned t = atomicAdd(&g_done, 1u);
        isLast = (t == gridDim.x - 1);
    }
    __syncthreads();
    if (isLast && threadIdx.x == 0) {
        float a0 = atomicAdd(&g_acc[0], 0.0f);
        float a1 = atomicAdd(&g_acc[1], 0.0f);
        float a2 = atomicAdd(&g_acc[2], 0.0f);
        float a3 = atomicAdd(&g_acc[3], 0.0f);
        float a4 = atomicAdd(&g_acc[4], 0.0f);
        float k  = fmaxf(a4, 1.0f);
        float lc = a0 / (3.0f * k);
        float ls = a1 / (3.0f * k);
        float lo = a2 / k;
        float li = a3 / k;
        out[0] = 1.0f * lc + 0.5f * (ls + lo) + 2.0f * li;
    }
}

// ---------------- launch ----------------
extern "C" void kernel_launch(void* const* d_in, const int* in_sizes, int n_in,
                              void* d_out, int out_size) {
    const float* pred = (const float*)d_in[0];
    const float* gt   = (const float*)d_in[1];
    int m = in_sizes[0] / 7;
    int n = in_sizes[1] / 7;

    init_kernel<<<(m + 255) / 256, 256>>>(m);

    int half = (m + 1) >> 1;
    dim3 g1((half + 255) / 256, (n + GT_TILE - 1) / GT_TILE);
    cand_kernel<<<g1, 256>>>(pred, gt, m, n);

    size_t smem = (size_t)MAXM * 8 * sizeof(unsigned short) + MAXM + MAXN;
    cudaFuncSetAttribute(match_kernel,
                         cudaFuncAttributeMaxDynamicSharedMemorySize,
                         (int)smem);
    match_kernel<<<1, 1024, smem>>>(m, n);

    loss_kernel<<<(m + 255) / 256, 256>>>(pred, gt, m, (float*)d_out);
}

// round 3
// speedup vs baseline: 2.5092x; 2.4564x over previous
#include <cuda_runtime.h>
#include <cstdint>

#define MAXM 8192
#define MAXN 8192
#define KCAND 64
#define GT_TILE 512

typedef unsigned long long u64;

// ---------------- device scratch (no allocations allowed) ----------------
__device__ int            g_cnt[MAXM];
__device__ u64            g_keys[MAXM * KCAND];    // (fbits(dsq)<<32)|j, arrival order
__device__ unsigned short g_sorted[MAXM * KCAND];  // per-row sorted gt indices
__device__ int            g_match[MAXM];           // matched gt index or -1
__device__ float          g_acc[5];                // Sc, Ss, So, Si, count
__device__ unsigned       g_done;

// ---------------- init ----------------
__global__ void init_kernel(int m) {
    int i = blockIdx.x * blockDim.x + threadIdx.x;
    if (i < m) g_cnt[i] = 0;
    if (i < 5) g_acc[i] = 0.0f;
    if (i == 0) g_done = 0u;
}

// ---------------- phase 1: candidate generation (full chip) ----------------
// Each thread owns TWO pred rows (i, i+m/2); gt centers staged in smem
// (warp-broadcast reads). Fused min-compare so the hit branch is one test.
__global__ void cand_kernel(const float* __restrict__ pred,
                            const float* __restrict__ gt,
                            int m, int n) {
    __shared__ float sx[GT_TILE], sy[GT_TILE], sz[GT_TILE];
    int jbase  = blockIdx.y * GT_TILE;
    int jcount = min(GT_TILE, n - jbase);
    for (int t = threadIdx.x; t < jcount; t += blockDim.x) {
        const float* g = gt + (size_t)(jbase + t) * 7;
        sx[t] = g[0]; sy[t] = g[1]; sz[t] = g[2];
    }
    __syncthreads();

    int half = (m + 1) >> 1;
    int i1 = blockIdx.x * blockDim.x + threadIdx.x;
    if (i1 >= half) return;
    int i2 = i1 + half;
    bool has2 = (i2 < m);

    float px1 = pred[i1 * 7 + 0], py1 = pred[i1 * 7 + 1], pz1 = pred[i1 * 7 + 2];
    float px2 = 1e30f, py2 = 1e30f, pz2 = 1e30f;
    if (has2) { px2 = pred[i2 * 7 + 0]; py2 = pred[i2 * 7 + 1]; pz2 = pred[i2 * 7 + 2]; }

    #pragma unroll 4
    for (int t = 0; t < jcount; ++t) {
        float gx = sx[t], gy = sy[t], gz = sz[t];
        float dx = px1 - gx, dy = py1 - gy, dz = pz1 - gz;
        float d1 = fmaf(dx, dx, fmaf(dy, dy, dz * dz));
        dx = px2 - gx; dy = py2 - gy; dz = pz2 - gz;
        float d2 = fmaf(dx, dx, fmaf(dy, dy, dz * dz));
        if (fminf(d1, d2) < 25.0f) {
            int j = jbase + t;
            if (d1 < 25.0f) {
                int p = atomicAdd(&g_cnt[i1], 1);
                if (p < KCAND)
                    g_keys[i1 * KCAND + p] =
                        ((u64)__float_as_uint(d1) << 32) | (unsigned)j;
            }
            if (d2 < 25.0f) {
                int p = atomicAdd(&g_cnt[i2], 1);
                if (p < KCAND)
                    g_keys[i2 * KCAND + p] =
                        ((u64)__float_as_uint(d2) << 32) | (unsigned)j;
            }
        }
    }
}

// ---------------- phase 2: per-row sort (full chip; counts ~4-5) -----------
__global__ void sort_kernel(int m) {
    int i = blockIdx.x * blockDim.x + threadIdx.x;
    if (i >= m) return;
    int nc = min(g_cnt[i], KCAND);
    g_cnt[i] = nc;
    u64 a[KCAND];
    for (int c = 0; c < nc; ++c) a[c] = g_keys[(size_t)i * KCAND + c];
    for (int c = 1; c < nc; ++c) {
        u64 v = a[c]; int d = c;
        while (d > 0 && a[d - 1] > v) { a[d] = a[d - 1]; --d; }
        a[d] = v;
    }
    for (int c = 0; c < nc; ++c)
        g_sorted[(size_t)i * KCAND + c] = (unsigned short)(a[c] & 0xFFFFu);
}

// ---------------- phase 3: parallel fixed-point greedy matcher -------------
// Single block, 1024 threads, 8 rows/thread. owner[j] = all-time minimum row
// index that ever proposed gt j (monotone non-increasing via atomicMin).
// A row advances past candidate j iff owner[j] < i. Safety: a displacement
// reason can only be superseded by a strictly smaller row index, so if any
// row was displaced at j by i', j's final owner is <= i' < i forever —
// advancing is always sound, no owner reset needed. The fixed point (no row
// advances) has all picks distinct with owner[j]==i, which is exactly the
// sequential greedy (row-priority, first-available over (dsq,j)-sorted
// candidates) outcome; the sort keys already reproduced serial argmin
// tie-breaking exactly in previous rounds.
__global__ void match_kernel(int m, int n) {
    __shared__ int s_owner[MAXN];
    const int R = MAXM / 1024;          // 8 rows per thread
    int tid = threadIdx.x;

    int ptr[R], cnt[R];
    #pragma unroll
    for (int r = 0; r < R; ++r) {
        int i = tid + r * 1024;
        cnt[r] = (i < m) ? g_cnt[i] : 0;
        ptr[r] = 0;
    }
    for (int j = tid; j < n; j += 1024) s_owner[j] = 0x7FFFFFFF;
    __syncthreads();

    for (;;) {
        // propose current candidates
        #pragma unroll
        for (int r = 0; r < R; ++r) {
            if (ptr[r] < cnt[r]) {
                int i = tid + r * 1024;
                int j = (int)g_sorted[(size_t)i * KCAND + ptr[r]];
                atomicMin(&s_owner[j], i);
            }
        }
        __syncthreads();
        // advance past candidates owned by smaller rows
        int ch = 0;
        #pragma unroll
        for (int r = 0; r < R; ++r) {
            int i = tid + r * 1024;
            while (ptr[r] < cnt[r]) {
                int j = (int)g_sorted[(size_t)i * KCAND + ptr[r]];
                if (s_owner[j] < i) { ++ptr[r]; ch = 1; }
                else break;
            }
        }
        if (!__syncthreads_or(ch)) break;
    }

    #pragma unroll
    for (int r = 0; r < R; ++r) {
        int i = tid + r * 1024;
        if (i < m) {
            g_match[i] = (ptr[r] < cnt[r])
                       ? (int)g_sorted[(size_t)i * KCAND + ptr[r]] : -1;
        }
    }
}

// ---------------- phase 4: loss reduction + fused finalize ----------------
__device__ __forceinline__ float sl1(float x) {
    float a = fabsf(x);
    return (a < 1.0f) ? 0.5f * a * a : a - 0.5f;
}

__global__ void loss_kernel(const float* __restrict__ pred,
                            const float* __restrict__ gt,
                            int m, float* out) {
    __shared__ bool isLast;
    int i = blockIdx.x * blockDim.x + threadIdx.x;
    float sc = 0.f, ss = 0.f, so = 0.f, si = 0.f, cf = 0.f;
    if (i < m) {
        int j = g_match[i];
        if (j >= 0) {
            cf = 1.0f;
            const float* p = pred + (size_t)i * 7;
            const float* g = gt + (size_t)j * 7;
            sc = sl1(p[0] - g[0]) + sl1(p[1] - g[1]) + sl1(p[2] - g[2]);
            ss = sl1(p[3] - g[3]) + sl1(p[4] - g[4]) + sl1(p[5] - g[5]);
            float dth = p[6] - g[6];
            dth = atan2f(sinf(dth), cosf(dth));
            so = sl1(dth);
            float x1 = p[0], y1 = p[1], l1 = p[3], w1 = p[4];
            float x2 = g[0], y2 = g[1], l2 = g[3], w2 = g[4];
            float iw = fminf(x1 + l1 * 0.5f, x2 + l2 * 0.5f)
                     - fmaxf(x1 - l1 * 0.5f, x2 - l2 * 0.5f);
            iw = fmaxf(iw, 0.0f);
            float ih = fminf(y1 + w1 * 0.5f, y2 + w2 * 0.5f)
                     - fmaxf(y1 - w1 * 0.5f, y2 - w2 * 0.5f);
            ih = fmaxf(ih, 0.0f);
            float inter = iw * ih;
            float uni = l1 * w1 + l2 * w2 - inter;
            si = 1.0f - inter / (uni + 1e-6f);
        }
    }
    #pragma unroll
    for (int o = 16; o; o >>= 1) {
        sc += __shfl_down_sync(0xFFFFFFFFu, sc, o);
        ss += __shfl_down_sync(0xFFFFFFFFu, ss, o);
        so += __shfl_down_sync(0xFFFFFFFFu, so, o);
        si += __shfl_down_sync(0xFFFFFFFFu, si, o);
        cf += __shfl_down_sync(0xFFFFFFFFu, cf, o);
    }
    if ((threadIdx.x & 31) == 0) {
        atomicAdd(&g_acc[0], sc);
        atomicAdd(&g_acc[1], ss);
        atomicAdd(&g_acc[2], so);
        atomicAdd(&g_acc[3], si);
        atomicAdd(&g_acc[4], cf);
    }
    __syncthreads();
    if (threadIdx.x == 0) {
        __threadfence();
        unsigned t = atomicAdd(&g_done, 1u);
        isLast = (t == gridDim.x - 1);
    }
    __syncthreads();
    if (isLast && threadIdx.x == 0) {
        float a0 = atomicAdd(&g_acc[0], 0.0f);
        float a1 = atomicAdd(&g_acc[1], 0.0f);
        float a2 = atomicAdd(&g_acc[2], 0.0f);
        float a3 = atomicAdd(&g_acc[3], 0.0f);
        float a4 = atomicAdd(&g_acc[4], 0.0f);
        float k  = fmaxf(a4, 1.0f);
        float lc = a0 / (3.0f * k);
        float ls = a1 / (3.0f * k);
        float lo = a2 / k;
        float li = a3 / k;
        out[0] = 1.0f * lc + 0.5f * (ls + lo) + 2.0f * li;
    }
}

// ---------------- launch ----------------
extern "C" void kernel_launch(void* const* d_in, const int* in_sizes, int n_in,
                              void* d_out, int out_size) {
    const float* pred = (const float*)d_in[0];
    const float* gt   = (const float*)d_in[1];
    int m = in_sizes[0] / 7;
    int n = in_sizes[1] / 7;

    init_kernel<<<(m + 255) / 256, 256>>>(m);

    int half = (m + 1) >> 1;
    dim3 g1((half + 255) / 256, (n + GT_TILE - 1) / GT_TILE);
    cand_kernel<<<g1, 256>>>(pred, gt, m, n);

    sort_kernel<<<(m + 127) / 128, 128>>>(m);

    match_kernel<<<1, 1024>>>(m, n);

    loss_kernel<<<(m + 127) / 128, 128>>>(pred, gt, m, (float*)d_out);
}

// round 4
// speedup vs baseline: 3.5209x; 1.4032x over previous
#include <cuda_runtime.h>
#include <cstdint>

#define MAXM        8192
#define MAXN        8192
#define GRID1       20
#define NCELLS      8000           // 20^3
#define NCELLS_PAD  8192
#define KC          24             // per-row candidate cap (overflow P ~ 4e-10)
#define CSTRIDE     32

typedef unsigned long long u64;

// ---------------- device scratch (no allocations allowed) ----------------
// g_cellcnt and g_done rely on static zero-init for the FIRST run and are
// re-zeroed by hist/loss for every subsequent run (deterministic).
__device__ int            g_cellcnt[NCELLS_PAD];     // zero-init; loss re-zeros
__device__ int            g_cellstart[NCELLS_PAD];
__device__ int            g_cellcur[NCELLS_PAD];
__device__ unsigned short g_cellgt[MAXN];            // gt ids grouped by cell
__device__ int            g_cnt[MAXM];
__device__ unsigned short g_sorted[MAXM * CSTRIDE];  // per-row (dsq,j)-sorted gt ids
__device__ int            g_match[MAXM];
__device__ float          g_acc[5];                  // zeroed by hist each run
__device__ unsigned       g_done;                    // zeroed by hist each run

__device__ __forceinline__ int cell1(float x) {
    int c = (int)floorf(x * 0.2f);
    return min(max(c, 0), GRID1 - 1);
}
__device__ __forceinline__ int cellid(float x, float y, float z) {
    return (cell1(z) * GRID1 + cell1(y)) * GRID1 + cell1(x);
}

// ---------------- build 1: histogram ----------------
__global__ void hist_kernel(const float* __restrict__ gt, int n) {
    int i = blockIdx.x * blockDim.x + threadIdx.x;
    if (i < 5) g_acc[i] = 0.0f;
    if (i == 5) g_done = 0u;
    if (i < n) {
        const float* g = gt + (size_t)i * 7;
        atomicAdd(&g_cellcnt[cellid(g[0], g[1], g[2])], 1);
    }
}

// ---------------- build 2: exclusive scan over 8192 cells (1 block) --------
__global__ void scan_kernel() {
    __shared__ int warpsum[32];
    int tid = threadIdx.x, lane = tid & 31, wid = tid >> 5;
    int base = tid * 8;
    int v[8], e[8], s = 0;
    #pragma unroll
    for (int k = 0; k < 8; ++k) v[k] = g_cellcnt[base + k];
    #pragma unroll
    for (int k = 0; k < 8; ++k) { e[k] = s; s += v[k]; }
    int x = s;
    #pragma unroll
    for (int o = 1; o < 32; o <<= 1) {
        int y = __shfl_up_sync(0xFFFFFFFFu, x, o);
        if (lane >= o) x += y;
    }
    if (lane == 31) warpsum[wid] = x;
    __syncthreads();
    if (wid == 0) {
        int w = warpsum[lane];
        int xx = w;
        #pragma unroll
        for (int o = 1; o < 32; o <<= 1) {
            int y = __shfl_up_sync(0xFFFFFFFFu, xx, o);
            if (lane >= o) xx += y;
        }
        warpsum[lane] = xx - w;      // exclusive warp offsets
    }
    __syncthreads();
    int off = warpsum[wid] + (x - s);
    #pragma unroll
    for (int k = 0; k < 8; ++k) {
        g_cellstart[base + k] = off + e[k];
        g_cellcur[base + k]   = off + e[k];
    }
}

// ---------------- build 3: scatter gt ids into cell lists ----------------
__global__ void scatter_kernel(const float* __restrict__ gt, int n) {
    int i = blockIdx.x * blockDim.x + threadIdx.x;
    if (i < n) {
        const float* g = gt + (size_t)i * 7;
        int c = cellid(g[0], g[1], g[2]);
        int p = atomicAdd(&g_cellcur[c], 1);
        g_cellgt[p] = (unsigned short)i;
    }
}

// ---------------- query + fused sort ----------------
// One thread per pred row. Neighborhood [cell1(px-5), cell1(px+5)] per dim is
// a guaranteed superset (f32 mul by 0.2 and floor are monotone), exact dsq<25
// test unchanged -> identical candidate sets to brute force. Candidates kept
// in a K=24 register array sorted by u64 key (dsq_bits<<32 | j) via min-sweep.
__global__ void query_kernel(const float* __restrict__ pred,
                             const float* __restrict__ gt,
                             int m, int n) {
    int i = blockIdx.x * blockDim.x + threadIdx.x;
    if (i >= m) return;
    float px = pred[i * 7 + 0], py = pred[i * 7 + 1], pz = pred[i * 7 + 2];

    u64 a[KC];
    #pragma unroll
    for (int k = 0; k < KC; ++k) a[k] = ~0ull;
    int cnt = 0;

    int x0 = cell1(px - 5.0f), x1 = cell1(px + 5.0f);
    int y0 = cell1(py - 5.0f), y1 = cell1(py + 5.0f);
    int z0 = cell1(pz - 5.0f), z1 = cell1(pz + 5.0f);

    for (int zz = z0; zz <= z1; ++zz) {
        for (int yy = y0; yy <= y1; ++yy) {
            int rowc = (zz * GRID1 + yy) * GRID1;
            int s = g_cellstart[rowc + x0];
            int e = g_cellstart[rowc + x1] + g_cellcnt[rowc + x1];
            for (int t = s; t < e; ++t) {
                int j = (int)g_cellgt[t];
                const float* g = gt + (size_t)j * 7;
                float dx = px - g[0], dy = py - g[1], dz = pz - g[2];
                float d = fmaf(dx, dx, fmaf(dy, dy, dz * dz));
                if (d < 25.0f) {
                    u64 key = ((u64)__float_as_uint(d) << 32) | (unsigned)j;
                    ++cnt;
                    #pragma unroll
                    for (int k = 0; k < KC; ++k) {   // sorted insert (min-sweep)
                        u64 mn = min(a[k], key);
                        key = a[k] ^ key ^ mn;
                        a[k] = mn;
                    }
                }
            }
        }
    }
    cnt = min(cnt, KC);
    g_cnt[i] = cnt;
    #pragma unroll
    for (int k = 0; k < KC; ++k)
        if (k < cnt)
            g_sorted[(size_t)i * CSTRIDE + k] = (unsigned short)(a[k] & 0xFFFFu);
}

// ---------------- match: work-list displacement fixed point ----------------
// owner[j] = all-time min proposing row (monotone via atomicMin). The winner
// of each decrease learns the displaced row from atomicMin's return value and
// pushes it into a queue; only pushed rows are reprocessed (after a barrier,
// so their s_ptr writes are visible). Fixed point == sequential greedy, as
// proven and verified in previous rounds. Outstanding queue entries <= one
// per row, so a MAXM ring never overwrites pending work.
extern __shared__ unsigned char smem_raw[];
__global__ void match_kernel(int m, int n) {
    int* s_owner = (int*)smem_raw;                       // MAXN ints
    int* s_queue = s_owner + MAXN;                       // MAXM ring
    unsigned char* s_ptr = (unsigned char*)(s_queue + MAXM);  // MAXM
    __shared__ int s_qtail, s_from;
    int tid = threadIdx.x;

    if (tid == 0) { s_qtail = 0; s_from = 0; }
    for (int j = tid; j < n; j += 1024) s_owner[j] = 0x7FFFFFFF;
    for (int i = tid; i < m; i += 1024) s_ptr[i] = 0;
    __syncthreads();

    auto chain = [&](int i) {
        int p = (int)s_ptr[i];
        int c = g_cnt[i];
        while (p < c) {
            int j = (int)g_sorted[(size_t)i * CSTRIDE + p];
            int old = atomicMin(&s_owner[j], i);
            if (old < i) { ++p; continue; }     // owned by smaller row: skip
            if (old != 0x7FFFFFFF && old > i) { // we displaced row 'old'
                int q = atomicAdd(&s_qtail, 1);
                s_queue[q & (MAXM - 1)] = old;
            }
            break;                               // parked (we own j)
        }
        s_ptr[i] = (unsigned char)p;
    };

    for (int i = tid; i < m; i += 1024) chain(i);
    __syncthreads();

    for (;;) {
        int t = s_qtail;            // uniform: read after barrier, no writes yet
        int f = s_from;
        if (f >= t) break;
        for (int idx = f + tid; idx < t; idx += 1024)
            chain(s_queue[idx & (MAXM - 1)]);
        __syncthreads();
        if (tid == 0) s_from = t;
        __syncthreads();
    }

    for (int i = tid; i < m; i += 1024) {
        int p = (int)s_ptr[i], c = g_cnt[i];
        g_match[i] = (p < c) ? (int)g_sorted[(size_t)i * CSTRIDE + p] : -1;
    }
}

// ---------------- loss reduction + fused finalize + cleanup ----------------
__device__ __forceinline__ float sl1(float x) {
    float a = fabsf(x);
    return (a < 1.0f) ? 0.5f * a * a : a - 0.5f;
}

__global__ void loss_kernel(const float* __restrict__ pred,
                            const float* __restrict__ gt,
                            int m, float* out) {
    __shared__ bool isLast;
    int i = blockIdx.x * blockDim.x + threadIdx.x;

    if (i < NCELLS_PAD) g_cellcnt[i] = 0;   // zero-state for the next replay

    float sc = 0.f, ss = 0.f, so = 0.f, si = 0.f, cf = 0.f;
    if (i < m) {
        int j = g_match[i];
        if (j >= 0) {
            cf = 1.0f;
            const float* p = pred + (size_t)i * 7;
            const float* g = gt + (size_t)j * 7;
            sc = sl1(p[0] - g[0]) + sl1(p[1] - g[1]) + sl1(p[2] - g[2]);
            ss = sl1(p[3] - g[3]) + sl1(p[4] - g[4]) + sl1(p[5] - g[5]);
            float dth = p[6] - g[6];
            dth = atan2f(sinf(dth), cosf(dth));
            so = sl1(dth);
            float x1 = p[0], y1 = p[1], l1 = p[3], w1 = p[4];
            float x2 = g[0], y2 = g[1], l2 = g[3], w2 = g[4];
            float iw = fminf(x1 + l1 * 0.5f, x2 + l2 * 0.5f)
                     - fmaxf(x1 - l1 * 0.5f, x2 - l2 * 0.5f);
            iw = fmaxf(iw, 0.0f);
            float ih = fminf(y1 + w1 * 0.5f, y2 + w2 * 0.5f)
                     - fmaxf(y1 - w1 * 0.5f, y2 - w2 * 0.5f);
            ih = fmaxf(ih, 0.0f);
            float inter = iw * ih;
            float uni = l1 * w1 + l2 * w2 - inter;
            si = 1.0f - inter / (uni + 1e-6f);
        }
    }
    #pragma unroll
    for (int o = 16; o; o >>= 1) {
        sc += __shfl_down_sync(0xFFFFFFFFu, sc, o);
        ss += __shfl_down_sync(0xFFFFFFFFu, ss, o);
        so += __shfl_down_sync(0xFFFFFFFFu, so, o);
        si += __shfl_down_sync(0xFFFFFFFFu, si, o);
        cf += __shfl_down_sync(0xFFFFFFFFu, cf, o);
    }
    if ((threadIdx.x & 31) == 0) {
        atomicAdd(&g_acc[0], sc);
        atomicAdd(&g_acc[1], ss);
        atomicAdd(&g_acc[2], so);
        atomicAdd(&g_acc[3], si);
        atomicAdd(&g_acc[4], cf);
    }
    __syncthreads();
    if (threadIdx.x == 0) {
        __threadfence();
        unsigned t = atomicAdd(&g_done, 1u);
        isLast = (t == gridDim.x - 1);
    }
    __syncthreads();
    if (isLast && threadIdx.x == 0) {
        float a0 = atomicAdd(&g_acc[0], 0.0f);
        float a1 = atomicAdd(&g_acc[1], 0.0f);
        float a2 = atomicAdd(&g_acc[2], 0.0f);
        float a3 = atomicAdd(&g_acc[3], 0.0f);
        float a4 = atomicAdd(&g_acc[4], 0.0f);
        float k  = fmaxf(a4, 1.0f);
        out[0] = a0 / (3.0f * k) + 0.5f * (a1 / (3.0f * k) + a2 / k)
               + 2.0f * (a3 / k);
    }
}

// ---------------- launch ----------------
extern "C" void kernel_launch(void* const* d_in, const int* in_sizes, int n_in,
                              void* d_out, int out_size) {
    const float* pred = (const float*)d_in[0];
    const float* gt   = (const float*)d_in[1];
    int m = in_sizes[0] / 7;
    int n = in_sizes[1] / 7;

    hist_kernel<<<(n + 255) / 256, 256>>>(gt, n);
    scan_kernel<<<1, 1024>>>();
    scatter_kernel<<<(n + 255) / 256, 256>>>(gt, n);
    query_kernel<<<(m + 127) / 128, 128>>>(pred, gt, m, n);

    size_t smem = (size_t)MAXN * 4 + (size_t)MAXM * 4 + MAXM;
    cudaFuncSetAttribute(match_kernel,
                         cudaFuncAttributeMaxDynamicSharedMemorySize,
                         (int)smem);
    match_kernel<<<1, 1024, smem>>>(m, n);

    loss_kernel<<<(m + 127) / 128, 128>>>(pred, gt, m, (float*)d_out);
}

// round 5
// speedup vs baseline: 4.1224x; 1.1708x over previous
#include <cuda_runtime.h>
#include <cstdint>

#define MAXM        8192
#define MAXN        8192
#define GRID1       20
#define NCELLS_PAD  8192
#define KC          24             // per-row candidate cap (overflow P ~ 4e-10)
#define CSTRIDE     32

typedef unsigned long long u64;

// ---------------- device scratch (no allocations allowed) ----------------
__device__ int            g_cellstart[NCELLS_PAD + 1];
__device__ float4         g_cellxyz[MAXN];            // (x,y,z,bitcast id), cell-grouped
__device__ uint4          g_row[MAXM];                // cnt | first 7 sorted candidates
__device__ unsigned short g_sorted[MAXM * CSTRIDE];   // overflow (pos >= 7)
__device__ int            g_match[MAXM];
__device__ float          g_acc[5];
__device__ unsigned       g_done;

__device__ __forceinline__ int cell1(float x) {
    int c = (int)floorf(x * 0.2f);
    return min(max(c, 0), GRID1 - 1);
}

// ---------------- build: hist + scan + scatter, one block ----------------
__global__ void build_kernel(const float* __restrict__ gt, int n) {
    __shared__ int s_cnt[NCELLS_PAD];   // hist -> cursor
    __shared__ int s_warp[32];
    int tid = threadIdx.x, lane = tid & 31, wid = tid >> 5;

    for (int c = tid; c < NCELLS_PAD; c += 1024) s_cnt[c] = 0;
    if (tid < 5) g_acc[tid] = 0.0f;
    if (tid == 5) g_done = 0u;
    __syncthreads();

    float gx[8], gy[8], gz[8];
    int myc[8];
    #pragma unroll
    for (int r = 0; r < 8; ++r) {
        int i = tid + r * 1024;
        myc[r] = -1;
        if (i < n) {
            const float* g = gt + (size_t)i * 7;
            gx[r] = g[0]; gy[r] = g[1]; gz[r] = g[2];
            int c = (cell1(gz[r]) * GRID1 + cell1(gy[r])) * GRID1 + cell1(gx[r]);
            myc[r] = c;
            atomicAdd(&s_cnt[c], 1);
        }
    }
    __syncthreads();

    // exclusive scan over 8192 cells (8 per thread)
    int base = tid * 8;
    int v[8], e[8], s = 0;
    #pragma unroll
    for (int k = 0; k < 8; ++k) v[k] = s_cnt[base + k];
    #pragma unroll
    for (int k = 0; k < 8; ++k) { e[k] = s; s += v[k]; }
    int x = s;
    #pragma unroll
    for (int o = 1; o < 32; o <<= 1) {
        int y = __shfl_up_sync(0xFFFFFFFFu, x, o);
        if (lane >= o) x += y;
    }
    if (lane == 31) s_warp[wid] = x;
    __syncthreads();
    if (wid == 0) {
        int w = s_warp[lane];
        int xx = w;
        #pragma unroll
        for (int o = 1; o < 32; o <<= 1) {
            int y = __shfl_up_sync(0xFFFFFFFFu, xx, o);
            if (lane >= o) xx += y;
        }
        s_warp[lane] = xx - w;
    }
    __syncthreads();
    int off = s_warp[wid] + (x - s);
    __syncthreads();                     // all s_cnt reads done before overwrite
    #pragma unroll
    for (int k = 0; k < 8; ++k) {
        g_cellstart[base + k] = off + e[k];
        s_cnt[base + k] = off + e[k];    // cursor
    }
    if (tid == 1023) g_cellstart[NCELLS_PAD] = off + e[7] + v[7];
    __syncthreads();

    // scatter packed float4
    #pragma unroll
    for (int r = 0; r < 8; ++r) {
        if (myc[r] >= 0) {
            int i = tid + r * 1024;
            int p = atomicAdd(&s_cnt[myc[r]], 1);
            g_cellxyz[p] = make_float4(gx[r], gy[r], gz[r], __int_as_float(i));
        }
    }
}

// ---------------- query + fused sort ----------------
// One thread per pred row. Per-dim neighborhood [cell1(px-5), cell1(px+5)] is
// a guaranteed superset (monotone f32 ops); exact dsq<25 test unchanged ->
// identical candidate sets to brute force. Candidates kept sorted by
// (fbits(dsq)<<32 | j) via register min-sweep (exact serial-argmin order).
__global__ void query_kernel(const float* __restrict__ pred, int m) {
    int i = blockIdx.x * blockDim.x + threadIdx.x;
    if (i >= m) return;
    float px = pred[i * 7 + 0], py = pred[i * 7 + 1], pz = pred[i * 7 + 2];

    u64 a[KC];
    #pragma unroll
    for (int k = 0; k < KC; ++k) a[k] = ~0ull;
    int cnt = 0;

    int x0 = cell1(px - 5.0f), x1 = cell1(px + 5.0f);
    int y0 = cell1(py - 5.0f), y1 = cell1(py + 5.0f);
    int z0 = cell1(pz - 5.0f), z1 = cell1(pz + 5.0f);

    for (int zz = z0; zz <= z1; ++zz) {
        for (int yy = y0; yy <= y1; ++yy) {
            int rowc = (zz * GRID1 + yy) * GRID1;
            int s = __ldg(&g_cellstart[rowc + x0]);
            int e = __ldg(&g_cellstart[rowc + x1 + 1]);
            for (int t = s; t < e; ++t) {
                float4 v = __ldg(&g_cellxyz[t]);
                float dx = px - v.x, dy = py - v.y, dz = pz - v.z;
                float d = fmaf(dx, dx, fmaf(dy, dy, dz * dz));
                if (d < 25.0f) {
                    u64 key = ((u64)__float_as_uint(d) << 32)
                            | (unsigned)__float_as_int(v.w);
                    ++cnt;
                    #pragma unroll
                    for (int k = 0; k < KC; ++k) {   // sorted insert (min-sweep)
                        u64 mn = min(a[k], key);
                        key = a[k] ^ key ^ mn;
                        a[k] = mn;
                    }
                }
            }
        }
    }
    cnt = min(cnt, KC);

    unsigned c[7];
    #pragma unroll
    for (int k = 0; k < 7; ++k) c[k] = (unsigned)(a[k] & 0xFFFFu);
    uint4 rv;
    rv.x = (unsigned)cnt | (c[0] << 16);
    rv.y = c[1] | (c[2] << 16);
    rv.z = c[3] | (c[4] << 16);
    rv.w = c[5] | (c[6] << 16);
    g_row[i] = rv;
    for (int k = 7; k < cnt; ++k)
        g_sorted[(size_t)i * CSTRIDE + k] = (unsigned short)(a[k] & 0xFFFFu);
}

// ---------------- match: work-list displacement fixed point ----------------
// owner[j] = all-time min proposing row (monotone via atomicMin). Winner of a
// decrease learns the displaced row from the return value, pushes it into a
// queue; only pushed rows are reprocessed after a barrier. Fixed point ==
// sequential greedy (verified rounds 1-4). <=1 outstanding entry per row, so
// a MAXM ring never overwrites pending work.
extern __shared__ unsigned char smem_raw[];
__global__ void match_kernel(int m, int n) {
    int* s_owner = (int*)smem_raw;                            // MAXN
    int* s_queue = s_owner + MAXN;                            // MAXM ring
    unsigned char* s_ptr = (unsigned char*)(s_queue + MAXM);  // MAXM
    __shared__ int s_qtail, s_from;
    int tid = threadIdx.x;

    if (tid == 0) { s_qtail = 0; s_from = 0; }
    for (int j = tid; j < n; j += 1024) s_owner[j] = 0x7FFFFFFF;
    for (int i = tid; i < m; i += 1024) s_ptr[i] = 0;
    __syncthreads();

    auto chain = [&](int i) {
        uint4 rv = __ldg(&g_row[i]);
        int c = (int)(rv.x & 0xFFFFu);
        int p = (int)s_ptr[i];
        while (p < c) {
            int j;
            if (p < 7) {
                unsigned w = (p == 0) ? rv.x
                           : (p < 3) ? rv.y
                           : (p < 5) ? rv.z : rv.w;
                int sh = (p == 0) ? 16 : ((p & 1) ? 0 : 16);
                j = (int)((w >> sh) & 0xFFFFu);
            } else {
                j = (int)g_sorted[(size_t)i * CSTRIDE + p];
            }
            int old = atomicMin(&s_owner[j], i);
            if (old < i) { ++p; continue; }      // owned by smaller row: skip
            if (old != 0x7FFFFFFF) {             // displaced row 'old' (> i)
                int q = atomicAdd(&s_qtail, 1);
                s_queue[q & (MAXM - 1)] = old;
            }
            break;                                // parked (we own j)
        }
        s_ptr[i] = (unsigned char)p;
    };

    for (int i = tid; i < m; i += 1024) chain(i);
    __syncthreads();

    for (;;) {
        int t = s_qtail;
        int f = s_from;
        if (f >= t) break;
        for (int idx = f + tid; idx < t; idx += 1024)
            chain(s_queue[idx & (MAXM - 1)]);
        __syncthreads();
        if (tid == 0) s_from = t;
        __syncthreads();
    }

    for (int i = tid; i < m; i += 1024) {
        uint4 rv = g_row[i];
        int c = (int)(rv.x & 0xFFFFu);
        int p = (int)s_ptr[i];
        int j = -1;
        if (p < c) {
            if (p < 7) {
                unsigned w = (p == 0) ? rv.x
                           : (p < 3) ? rv.y
                           : (p < 5) ? rv.z : rv.w;
                int sh = (p == 0) ? 16 : ((p & 1) ? 0 : 16);
                j = (int)((w >> sh) & 0xFFFFu);
            } else {
                j = (int)g_sorted[(size_t)i * CSTRIDE + p];
            }
        }
        g_match[i] = j;
    }
}

// ---------------- loss reduction + fused finalize ----------------
__device__ __forceinline__ float sl1(float x) {
    float a = fabsf(x);
    return (a < 1.0f) ? 0.5f * a * a : a - 0.5f;
}

__global__ void loss_kernel(const float* __restrict__ pred,
                            const float* __restrict__ gt,
                            int m, float* out) {
    __shared__ bool isLast;
    int i = blockIdx.x * blockDim.x + threadIdx.x;
    float sc = 0.f, ss = 0.f, so = 0.f, si = 0.f, cf = 0.f;
    if (i < m) {
        int j = g_match[i];
        if (j >= 0) {
            cf = 1.0f;
            const float* p = pred + (size_t)i * 7;
            const float* g = gt + (size_t)j * 7;
            sc = sl1(p[0] - g[0]) + sl1(p[1] - g[1]) + sl1(p[2] - g[2]);
            ss = sl1(p[3] - g[3]) + sl1(p[4] - g[4]) + sl1(p[5] - g[5]);
            float dth = p[6] - g[6];
            dth = atan2f(sinf(dth), cosf(dth));
            so = sl1(dth);
            float x1 = p[0], y1 = p[1], l1 = p[3], w1 = p[4];
            float x2 = g[0], y2 = g[1], l2 = g[3], w2 = g[4];
            float iw = fminf(x1 + l1 * 0.5f, x2 + l2 * 0.5f)
                     - fmaxf(x1 - l1 * 0.5f, x2 - l2 * 0.5f);
            iw = fmaxf(iw, 0.0f);
            float ih = fminf(y1 + w1 * 0.5f, y2 + w2 * 0.5f)
                     - fmaxf(y1 - w1 * 0.5f, y2 - w2 * 0.5f);
            ih = fmaxf(ih, 0.0f);
            float inter = iw * ih;
            float uni = l1 * w1 + l2 * w2 - inter;
            si = 1.0f - inter / (uni + 1e-6f);
        }
    }
    #pragma unroll
    for (int o = 16; o; o >>= 1) {
        sc += __shfl_down_sync(0xFFFFFFFFu, sc, o);
        ss += __shfl_down_sync(0xFFFFFFFFu, ss, o);
        so += __shfl_down_sync(0xFFFFFFFFu, so, o);
        si += __shfl_down_sync(0xFFFFFFFFu, si, o);
        cf += __shfl_down_sync(0xFFFFFFFFu, cf, o);
    }
    if ((threadIdx.x & 31) == 0) {
        atomicAdd(&g_acc[0], sc);
        atomicAdd(&g_acc[1], ss);
        atomicAdd(&g_acc[2], so);
        atomicAdd(&g_acc[3], si);
        atomicAdd(&g_acc[4], cf);
    }
    __syncthreads();
    if (threadIdx.x == 0) {
        __threadfence();
        unsigned t = atomicAdd(&g_done, 1u);
        isLast = (t == gridDim.x - 1);
    }
    __syncthreads();
    if (isLast && threadIdx.x == 0) {
        float a0 = atomicAdd(&g_acc[0], 0.0f);
        float a1 = atomicAdd(&g_acc[1], 0.0f);
        float a2 = atomicAdd(&g_acc[2], 0.0f);
        float a3 = atomicAdd(&g_acc[3], 0.0f);
        float a4 = atomicAdd(&g_acc[4], 0.0f);
        float k  = fmaxf(a4, 1.0f);
        out[0] = a0 / (3.0f * k) + 0.5f * (a1 / (3.0f * k) + a2 / k)
               + 2.0f * (a3 / k);
    }
}

// ---------------- launch ----------------
extern "C" void kernel_launch(void* const* d_in, const int* in_sizes, int n_in,
                              void* d_out, int out_size) {
    const float* pred = (const float*)d_in[0];
    const float* gt   = (const float*)d_in[1];
    int m = in_sizes[0] / 7;
    int n = in_sizes[1] / 7;

    build_kernel<<<1, 1024>>>(gt, n);

    query_kernel<<<(m + 63) / 64, 64>>>(pred, m);

    size_t smem = (size_t)MAXN * 4 + (size_t)MAXM * 4 + MAXM;
    cudaFuncSetAttribute(match_kernel,
                         cudaFuncAttributeMaxDynamicSharedMemorySize,
                         (int)smem);
    match_kernel<<<1, 1024, smem>>>(m, n);

    loss_kernel<<<(m + 127) / 128, 128>>>(pred, gt, m, (float*)d_out);
}